// round 3
// baseline (speedup 1.0000x reference)
#include <cuda_runtime.h>
#include <cuda_bf16.h>
#include <math.h>
#include <stdint.h>

// Problem dims
#define B_   32
#define T_   512
#define IN_  128
#define H_   1024
#define OUT_ 128

// Persistent kernel config
#define NCTA 128
#define NTHR 256
#define KT   128

// SMEM layout (floats)
#define AS_OFF  0        // 2 * 32 * 132 = 8448
#define WS_OFF  8448     // 2 * 32 * 132 = 8448
#define RED_OFF 16896    // 8 * 32 * 32  = 8192
#define G_OFF   25088    // 32 * 33      = 1056
#define BS_OFF  26144    // 64
#define CS_OFF  26208    // 2 * 256      = 512
#define SMEM_FLOATS 26720
#define SMEM_BYTES  (SMEM_FLOATS * 4)

// ---------------------------------------------------------------------------
// Device scratch (__device__ globals: allocation-free rule)
// ---------------------------------------------------------------------------
__device__ float d_E [T_ * B_ * H_];     // embed output  [t][b][h]  (64 MB)
__device__ float d_H1[T_ * B_ * H_];     // layer-1 h     [t][b][h]  (64 MB)
__device__ float d_hbuf[2][2][B_ * H_];  // [layer][parity][b*H+h]
__device__ unsigned g_arrive;
__device__ unsigned g_release;

// ---------------------------------------------------------------------------
// cp.async helpers
// ---------------------------------------------------------------------------
__device__ __forceinline__ void cpasync16(uint32_t dst, const void* src) {
    asm volatile("cp.async.cg.shared.global [%0], [%1], 16;\n" :: "r"(dst), "l"(src));
}
__device__ __forceinline__ void cpcommit() {
    asm volatile("cp.async.commit_group;\n");
}
template <int N>
__device__ __forceinline__ void cpwait() {
    asm volatile("cp.async.wait_group %0;\n" :: "n"(N));
}

// ---------------------------------------------------------------------------
// Grid barrier: generation-counting, monotone counters (reset by embed kernel)
// ---------------------------------------------------------------------------
__device__ __forceinline__ void gridbar(unsigned gen) {
    __threadfence();            // all threads: make prior global writes visible
    __syncthreads();
    if (threadIdx.x == 0) {
        unsigned a = atomicAdd(&g_arrive, 1u) + 1u;
        if (a == (unsigned)NCTA * gen) {
            atomicExch(&g_release, gen);
        } else {
            while (*((volatile unsigned*)&g_release) < gen) {
                __nanosleep(32);
            }
        }
    }
    __syncthreads();
}

// ---------------------------------------------------------------------------
// Embed kernel: E[t][b][h] = x[b][t][:] . W_embed[h][:] + b_embed[h]
// grid (4, T_), block 256
// ---------------------------------------------------------------------------
__global__ void embed_kernel(const float* __restrict__ x,
                             const float* __restrict__ Wemb,
                             const float* __restrict__ bemb) {
    __shared__ float xs[B_][IN_];
    const int t   = blockIdx.y;
    const int tid = threadIdx.x;

    if (blockIdx.x == 0 && blockIdx.y == 0 && tid == 0) {
        g_arrive  = 0u;       // reset barrier state for the persistent kernel
        g_release = 0u;
    }

    for (int i = tid; i < B_ * IN_; i += 256) {
        int b = i >> 7, k = i & 127;
        xs[b][k] = x[(b * T_ + t) * IN_ + k];
    }
    __syncthreads();

    const int h = blockIdx.x * 256 + tid;
    const float4* wr = (const float4*)(Wemb + h * IN_);
    float acc[B_];
    const float bv = bemb[h];
#pragma unroll
    for (int b = 0; b < B_; b++) acc[b] = bv;

#pragma unroll 4
    for (int k4 = 0; k4 < IN_ / 4; k4++) {
        float4 w = wr[k4];
        int k = k4 * 4;
#pragma unroll
        for (int b = 0; b < B_; b++) {
            acc[b] += xs[b][k] * w.x + xs[b][k + 1] * w.y +
                      xs[b][k + 2] * w.z + xs[b][k + 3] * w.w;
        }
    }
#pragma unroll
    for (int b = 0; b < B_; b++) d_E[(t * B_ + b) * H_ + h] = acc[b];
}

// ---------------------------------------------------------------------------
// Output kernel: out[b][t][o] = H1[t][b][:] . W_out[o][:] + b_out[o]
// grid T_, block 128
// ---------------------------------------------------------------------------
__global__ void out_kernel(const float* __restrict__ Wout,
                           const float* __restrict__ bout,
                           float* __restrict__ out) {
    __shared__ float hs[B_][128];
    const int t   = blockIdx.x;
    const int tid = threadIdx.x;   // o index

    float acc[B_];
    const float bv = bout[tid];
#pragma unroll
    for (int b = 0; b < B_; b++) acc[b] = bv;

    for (int kc = 0; kc < H_; kc += 128) {
        __syncthreads();
        for (int i = tid; i < B_ * 128; i += 128) {
            int b = i >> 7, k = i & 127;
            hs[b][k] = d_H1[(t * B_ + b) * H_ + kc + k];
        }
        __syncthreads();
        const float4* wr = (const float4*)(Wout + tid * H_ + kc);
#pragma unroll 4
        for (int k4 = 0; k4 < 32; k4++) {
            float4 w = wr[k4];
            int k = k4 * 4;
#pragma unroll
            for (int b = 0; b < B_; b++) {
                acc[b] += hs[b][k] * w.x + hs[b][k + 1] * w.y +
                          hs[b][k + 2] * w.z + hs[b][k + 3] * w.w;
            }
        }
    }
#pragma unroll
    for (int b = 0; b < B_; b++) out[(b * T_ + t) * OUT_ + tid] = acc[b];
}

// ---------------------------------------------------------------------------
// One LSTM phase for one layer: this CTA computes 32 gate rows
//   j = (n>>3)*1024 + r*8 + (n&7),  n = 0..31   (q = n>>3 selects i/f/g/o)
// gates[b][n] = sum_k Xin[b][k] Wih[j][k] + sum_k Hprev[b][k] Whh[j][k] + bias
// ---------------------------------------------------------------------------
__device__ __forceinline__ void lstm_phase(
    float* sm, uint32_t smbase, int r, int tid, int kg, int pos_n, int pos_b,
    const float* __restrict__ Xin,    // [32][1024]
    const float* __restrict__ Hprev,  // [32][1024]
    const float* __restrict__ Wih_l,  // [4096][1024]
    const float* __restrict__ Whh_l,  // [4096][1024]
    int l,
    float* __restrict__ hout,         // [32][1024] — write our 8 units
    float* __restrict__ h1out)        // optional extra dest (d_H1 slab) or null
{
    float acc[4][8];
#pragma unroll
    for (int i = 0; i < 4; i++)
#pragma unroll
        for (int j = 0; j < 8; j++) acc[i][j] = 0.f;

    auto load_tile = [&](int tile, int dbuf) {
        const float* asrc = (tile < 8) ? (Xin + tile * KT) : (Hprev + (tile - 8) * KT);
        const float* wb   = (tile < 8) ? Wih_l : Whh_l;
        const int koff    = (tile & 7) * KT;
#pragma unroll
        for (int rep = 0; rep < 4; rep++) {
            int idx = rep * 256 + tid;
            int row = idx >> 5;
            int kf  = (idx & 31) * 4;
            uint32_t adst = smbase + (uint32_t)(AS_OFF + dbuf * 4224 + row * 132 + kf) * 4u;
            cpasync16(adst, asrc + row * H_ + kf);
            int j = ((row >> 3) << 10) + (r << 3) + (row & 7);
            uint32_t wdst = smbase + (uint32_t)(WS_OFF + dbuf * 4224 + row * 132 + kf) * 4u;
            cpasync16(wdst, wb + j * H_ + koff + kf);
        }
    };

    int buf = 0;
    load_tile(0, 0);
    cpcommit();

#pragma unroll 1
    for (int tile = 0; tile < 16; tile++) {
        if (tile < 15) {
            load_tile(tile + 1, buf ^ 1);
            cpcommit();
            cpwait<1>();
        } else {
            cpwait<0>();
        }
        __syncthreads();

        const float* A = sm + AS_OFF + buf * 4224;
        const float* W = sm + WS_OFF + buf * 4224;
        const int k0 = kg * 16;
#pragma unroll
        for (int kk = 0; kk < 16; kk++) {
            const int k = k0 + kk;
            float a[4], w[8];
#pragma unroll
            for (int i = 0; i < 4; i++) a[i] = A[(pos_b + 8 * i) * 132 + k];
#pragma unroll
            for (int j = 0; j < 8; j++) w[j] = W[(pos_n + 4 * j) * 132 + k];
#pragma unroll
            for (int i = 0; i < 4; i++)
#pragma unroll
                for (int j = 0; j < 8; j++) acc[i][j] += a[i] * w[j];
        }
        buf ^= 1;
        __syncthreads();
    }

    // k-split reduction: Red[kg][n][b]
    float* Red = sm + RED_OFF;
#pragma unroll
    for (int i = 0; i < 4; i++)
#pragma unroll
        for (int j = 0; j < 8; j++)
            Red[kg * 1024 + (pos_n + 4 * j) * 32 + (pos_b + 8 * i)] = acc[i][j];
    __syncthreads();

    float* G = sm + G_OFF;
#pragma unroll
    for (int ii = 0; ii < 4; ii++) {
        int o = tid * 4 + ii;
        int n = o >> 5, b = o & 31;
        float s = sm[BS_OFF + l * 32 + n];
#pragma unroll
        for (int g = 0; g < 8; g++) s += Red[g * 1024 + n * 32 + b];
        G[n * 33 + b] = s;
    }
    __syncthreads();

    // elementwise LSTM cell: one (b, uu) per thread
    {
        const int b  = tid >> 3;
        const int uu = tid & 7;
        float gi = G[(uu) * 33 + b];
        float gf = G[(8 + uu) * 33 + b];
        float gg = G[(16 + uu) * 33 + b];
        float go = G[(24 + uu) * 33 + b];
        float cOld = sm[CS_OFF + l * 256 + tid];
        float si = 1.f / (1.f + __expf(-gi));
        float sf = 1.f / (1.f + __expf(-gf));
        float so = 1.f / (1.f + __expf(-go));
        float cN = sf * cOld + si * tanhf(gg);
        float hN = so * tanhf(cN);
        sm[CS_OFF + l * 256 + tid] = cN;
        const int u = r * 8 + uu;
        __stcg(&hout[b * H_ + u], hN);
        if (h1out) __stcg(&h1out[b * H_ + u], hN);
    }
    __syncthreads();
}

// ---------------------------------------------------------------------------
// Persistent LSTM kernel: 128 CTAs, 512 steps, 2 layers
// ---------------------------------------------------------------------------
__global__ void __launch_bounds__(NTHR, 1) lstm_persistent(
    const float* __restrict__ Wih, const float* __restrict__ bih,
    const float* __restrict__ Whh, const float* __restrict__ bhh,
    const float* __restrict__ h0)
{
    extern __shared__ float sm[];
    const int tid   = threadIdx.x;
    const int r     = blockIdx.x;
    const int kg    = tid >> 5;
    const int lane  = tid & 31;
    const int pos_n = lane >> 3;   // 0..3
    const int pos_b = lane & 7;    // 0..7
    const uint32_t smbase = (uint32_t)__cvta_generic_to_shared(sm);

    // biases for this CTA's 32 gate rows, both layers
    if (tid < 64) {
        int l = tid >> 5, n = tid & 31;
        int j = ((n >> 3) << 10) + (r << 3) + (n & 7);
        sm[BS_OFF + tid] = bih[l * 4 * H_ + j] + bhh[l * 4 * H_ + j];
    }
    // init h (global, parity 0) and c (SMEM) from h0: [B][L*2*H], (h, c) per layer
    {
        const int b = tid >> 3, uu = tid & 7;
        const int u = r * 8 + uu;
        const int base = b * (4 * H_);
        float h_l0 = h0[base + 0 * 2 * H_ + u];
        float c_l0 = h0[base + 0 * 2 * H_ + H_ + u];
        float h_l1 = h0[base + 1 * 2 * H_ + u];
        float c_l1 = h0[base + 1 * 2 * H_ + H_ + u];
        __stcg(&d_hbuf[0][0][b * H_ + u], h_l0);
        __stcg(&d_hbuf[1][0][b * H_ + u], h_l1);
        sm[CS_OFF + 0 * 256 + tid] = c_l0;
        sm[CS_OFF + 1 * 256 + tid] = c_l1;
    }
    __syncthreads();

    unsigned gen = 0;
    gridbar(++gen);   // all h initialized

    const float* Wih0 = Wih;
    const float* Wih1 = Wih + 4 * H_ * H_;
    const float* Whh0 = Whh;
    const float* Whh1 = Whh + 4 * H_ * H_;

#pragma unroll 1
    for (int t = 0; t < T_; t++) {
        const int p = t & 1;
        // layer 0: Xin = E[t], Hprev = hbuf0[p] -> hbuf0[1-p]
        lstm_phase(sm, smbase, r, tid, kg, pos_n, pos_b,
                   d_E + (size_t)t * B_ * H_, d_hbuf[0][p],
                   Wih0, Whh0, 0, d_hbuf[0][1 - p], (float*)0);
        gridbar(++gen);
        // layer 1: Xin = hbuf0[1-p], Hprev = hbuf1[p] -> hbuf1[1-p], H1[t]
        lstm_phase(sm, smbase, r, tid, kg, pos_n, pos_b,
                   d_hbuf[0][1 - p], d_hbuf[1][p],
                   Wih1, Whh1, 1, d_hbuf[1][1 - p],
                   d_H1 + (size_t)t * B_ * H_);
        // no barrier needed here: next step's barrier (after its phase 0)
        // orders phase1(t) writes before phase1(t+1) reads; phase0(t+1)
        // touches only hbuf0 buffers already ordered by barrier #t.
    }
}

// ---------------------------------------------------------------------------
extern "C" void kernel_launch(void* const* d_in, const int* in_sizes, int n_in,
                              void* d_out, int out_size) {
    const float* x       = (const float*)d_in[0];
    const float* W_embed = (const float*)d_in[1];
    const float* b_embed = (const float*)d_in[2];
    const float* W_ih    = (const float*)d_in[3];
    const float* b_ih    = (const float*)d_in[4];
    const float* W_hh    = (const float*)d_in[5];
    const float* b_hh    = (const float*)d_in[6];
    const float* W_out   = (const float*)d_in[7];
    const float* b_out   = (const float*)d_in[8];
    const float* h0      = (const float*)d_in[9];
    float* out = (float*)d_out;

    cudaFuncSetAttribute(lstm_persistent,
                         cudaFuncAttributeMaxDynamicSharedMemorySize, SMEM_BYTES);

    embed_kernel<<<dim3(4, T_), 256>>>(x, W_embed, b_embed);
    lstm_persistent<<<NCTA, NTHR, SMEM_BYTES>>>(W_ih, b_ih, W_hh, b_hh, h0);
    out_kernel<<<T_, 128>>>(W_out, b_out, out);
}

// round 4
// speedup vs baseline: 1.9319x; 1.9319x over previous
#include <cuda_runtime.h>
#include <cuda_bf16.h>
#include <math.h>
#include <stdint.h>

// Problem dims
#define B_   32
#define T_   512
#define IN_  128
#define H_   1024
#define OUT_ 128

// Persistent kernel config
#define NCTA 128
#define NTHR 256
#define KC   256            // K elems per chunk
#define NCHK 8              // 2048 / 256
#define ROWB 512            // bytes per tile row (256 bf16)
#define TILEB 16384         // 32 rows * 512 B
#define BUFB  65536         // 4 tiles per buffer

// SMEM byte offsets
#define G_B   131072        // 32*33 f32 = 4224
#define BS_B  135296        // 64 f32    = 256
#define CS_B  135552        // 512 f32   = 2048
#define SMEM_BYTES 137600

typedef __nv_bfloat16 bf16;

// ---------------------------------------------------------------------------
// Device scratch
// ---------------------------------------------------------------------------
__device__ bf16  d_Ehi[T_ * B_ * H_];
__device__ bf16  d_Elo[T_ * B_ * H_];
__device__ float d_H1 [T_ * B_ * H_];
__device__ bf16  d_hh[2][2][B_ * H_];   // [layer][parity] h hi
__device__ bf16  d_hl[2][2][B_ * H_];   // [layer][parity] h lo
__device__ bf16  d_Wh[2 * 128 * 32 * 2048];   // per (layer, cta) gathered hi
__device__ bf16  d_Wl[2 * 128 * 32 * 2048];   // per (layer, cta) gathered lo
__device__ unsigned g_arrive;
__device__ unsigned g_release;

// ---------------------------------------------------------------------------
// PTX helpers
// ---------------------------------------------------------------------------
__device__ __forceinline__ void cpasync16(uint32_t dst, const void* src) {
    asm volatile("cp.async.cg.shared.global [%0], [%1], 16;\n" :: "r"(dst), "l"(src));
}
__device__ __forceinline__ void cpcommit() {
    asm volatile("cp.async.commit_group;\n");
}
template <int N>
__device__ __forceinline__ void cpwait() {
    asm volatile("cp.async.wait_group %0;\n" :: "n"(N));
}
__device__ __forceinline__ void ldsm_x4(uint32_t* r, uint32_t addr) {
    asm volatile("ldmatrix.sync.aligned.m8n8.x4.shared.b16 {%0,%1,%2,%3}, [%4];\n"
                 : "=r"(r[0]), "=r"(r[1]), "=r"(r[2]), "=r"(r[3]) : "r"(addr));
}
__device__ __forceinline__ void ldsm_x2(uint32_t* r, uint32_t addr) {
    asm volatile("ldmatrix.sync.aligned.m8n8.x2.shared.b16 {%0,%1}, [%2];\n"
                 : "=r"(r[0]), "=r"(r[1]) : "r"(addr));
}
__device__ __forceinline__ void mma_bf16(float* c, const uint32_t* a, const uint32_t* b) {
    asm volatile("mma.sync.aligned.m16n8k16.row.col.f32.bf16.bf16.f32 "
                 "{%0,%1,%2,%3}, {%4,%5,%6,%7}, {%8,%9}, {%0,%1,%2,%3};\n"
                 : "+f"(c[0]), "+f"(c[1]), "+f"(c[2]), "+f"(c[3])
                 : "r"(a[0]), "r"(a[1]), "r"(a[2]), "r"(a[3]), "r"(b[0]), "r"(b[1]));
}
__device__ __forceinline__ void st_bf16_cg(bf16* p, bf16 v) {
    unsigned short b = __bfloat16_as_ushort(v);
    asm volatile("st.global.cg.u16 [%0], %1;" :: "l"(p), "h"(b));
}

// ---------------------------------------------------------------------------
// Grid barrier
// ---------------------------------------------------------------------------
__device__ __forceinline__ void gridbar(unsigned gen) {
    __threadfence();
    __syncthreads();
    if (threadIdx.x == 0) {
        unsigned a = atomicAdd(&g_arrive, 1u) + 1u;
        if (a == (unsigned)NCTA * gen) {
            atomicExch(&g_release, gen);
        } else {
            while (*((volatile unsigned*)&g_release) < gen) __nanosleep(32);
        }
    }
    __syncthreads();
}

// ---------------------------------------------------------------------------
// Weight prep: gather + bf16 hi/lo split into per-CTA contiguous blocks.
//   dst[(l*128+r)][m][k], m=0..31 local gate row (j = (m>>3)*1024 + r*8 + (m&7)),
//   k<1024 -> Wih[l][j][k], else Whh[l][j][k-1024]
// ---------------------------------------------------------------------------
__global__ void prep_weights(const float* __restrict__ Wih,
                             const float* __restrict__ Whh) {
    const int r = blockIdx.x, l = blockIdx.y;
    const size_t dstbase = ((size_t)l * 128 + r) * 32 * 2048;
    for (int idx = threadIdx.x; idx < 32 * 2048; idx += 256) {
        int m = idx >> 11, k = idx & 2047;
        int j = ((m >> 3) << 10) + (r << 3) + (m & 7);
        float f = (k < 1024) ? Wih[((size_t)l * 4096 + j) * 1024 + k]
                             : Whh[((size_t)l * 4096 + j) * 1024 + (k - 1024)];
        bf16 hi = __float2bfloat16(f);
        bf16 lo = __float2bfloat16(f - __bfloat162float(hi));
        d_Wh[dstbase + idx] = hi;
        d_Wl[dstbase + idx] = lo;
    }
}

// ---------------------------------------------------------------------------
// Embed kernel: E[t][b][h] = x[b][t][:] . W_embed[h][:] + b_embed[h] -> bf16 hi/lo
// ---------------------------------------------------------------------------
__global__ void embed_kernel(const float* __restrict__ x,
                             const float* __restrict__ Wemb,
                             const float* __restrict__ bemb) {
    __shared__ float xs[B_][IN_];
    const int t   = blockIdx.y;
    const int tid = threadIdx.x;

    if (blockIdx.x == 0 && blockIdx.y == 0 && tid == 0) {
        g_arrive  = 0u;
        g_release = 0u;
    }

    for (int i = tid; i < B_ * IN_; i += 256) {
        int b = i >> 7, k = i & 127;
        xs[b][k] = x[(b * T_ + t) * IN_ + k];
    }
    __syncthreads();

    const int h = blockIdx.x * 256 + tid;
    const float4* wr = (const float4*)(Wemb + h * IN_);
    float acc[B_];
    const float bv = bemb[h];
#pragma unroll
    for (int b = 0; b < B_; b++) acc[b] = bv;

#pragma unroll 4
    for (int k4 = 0; k4 < IN_ / 4; k4++) {
        float4 w = wr[k4];
        int k = k4 * 4;
#pragma unroll
        for (int b = 0; b < B_; b++) {
            acc[b] += xs[b][k] * w.x + xs[b][k + 1] * w.y +
                      xs[b][k + 2] * w.z + xs[b][k + 3] * w.w;
        }
    }
#pragma unroll
    for (int b = 0; b < B_; b++) {
        bf16 hi = __float2bfloat16(acc[b]);
        bf16 lo = __float2bfloat16(acc[b] - __bfloat162float(hi));
        d_Ehi[(t * B_ + b) * H_ + h] = hi;
        d_Elo[(t * B_ + b) * H_ + h] = lo;
    }
}

// ---------------------------------------------------------------------------
// Output kernel: out[b][t][o] = H1[t][b][:] . W_out[o][:] + b_out[o]
// ---------------------------------------------------------------------------
__global__ void out_kernel(const float* __restrict__ Wout,
                           const float* __restrict__ bout,
                           float* __restrict__ out) {
    __shared__ float hs[B_][128];
    const int t   = blockIdx.x;
    const int tid = threadIdx.x;

    float acc[B_];
    const float bv = bout[tid];
#pragma unroll
    for (int b = 0; b < B_; b++) acc[b] = bv;

    for (int kc = 0; kc < H_; kc += 128) {
        __syncthreads();
        for (int i = tid; i < B_ * 128; i += 128) {
            int b = i >> 7, k = i & 127;
            hs[b][k] = d_H1[(t * B_ + b) * H_ + kc + k];
        }
        __syncthreads();
        const float4* wr = (const float4*)(Wout + tid * H_ + kc);
#pragma unroll 4
        for (int k4 = 0; k4 < 32; k4++) {
            float4 w = wr[k4];
            int k = k4 * 4;
#pragma unroll
            for (int b = 0; b < B_; b++) {
                acc[b] += hs[b][k] * w.x + hs[b][k + 1] * w.y +
                          hs[b][k + 2] * w.z + hs[b][k + 3] * w.w;
            }
        }
    }
#pragma unroll
    for (int b = 0; b < B_; b++) out[(b * T_ + t) * OUT_ + tid] = acc[b];
}

// ---------------------------------------------------------------------------
// Load one K-chunk (KC=256) of all 4 tiles into smem buffer `buf`.
// Tiles: 0 = W_hi, 1 = W_lo, 2 = Act_hi, 3 = Act_lo.  XOR-16B swizzle per row.
// ---------------------------------------------------------------------------
__device__ __forceinline__ void load_chunk(
    uint32_t smbase, int buf, int tid, int c,
    const bf16* __restrict__ Wh, const bf16* __restrict__ Wl,
    const bf16* __restrict__ Xh, const bf16* __restrict__ Xl,
    const bf16* __restrict__ Hh, const bf16* __restrict__ Hl)
{
#pragma unroll
    for (int rep = 0; rep < 16; rep++) {
        const int tile = rep >> 2;               // 4 reps per tile
        const int row  = ((rep & 3) << 3) + (tid >> 5);
        const int ch   = tid & 31;
        uint32_t dst = smbase + buf * BUFB + tile * TILEB + row * ROWB
                     + (uint32_t)((ch << 4) ^ ((row & 7) << 4));
        const bf16* src;
        if (tile == 0)      src = Wh + row * 2048 + c * KC;
        else if (tile == 1) src = Wl + row * 2048 + c * KC;
        else {
            const bf16* base = (c < 4) ? ((tile == 2) ? Xh : Xl)
                                       : ((tile == 2) ? Hh : Hl);
            int koff = (c < 4) ? c * KC : (c - 4) * KC;
            src = base + row * H_ + koff;
        }
        cpasync16(dst, src + ch * 8);
    }
}

// ---------------------------------------------------------------------------
// One LSTM phase: per CTA 32 gate rows x 32 batch x K=2048 via bf16-split mma.
// ---------------------------------------------------------------------------
__device__ __forceinline__ void lstm_phase(
    char* smc, uint32_t smbase, int tid, int r, int l,
    const bf16* __restrict__ Wh, const bf16* __restrict__ Wl,
    const bf16* __restrict__ Xh, const bf16* __restrict__ Xl,
    const bf16* __restrict__ Hh, const bf16* __restrict__ Hl,
    bf16* __restrict__ houth, bf16* __restrict__ houtl,
    float* __restrict__ h1out)
{
    const int wid  = tid >> 5;
    const int lane = tid & 31;
    const int m_off = (wid & 1) << 4;    // 0 or 16
    const int n_off = (wid >> 1) << 3;   // 0,8,16,24

    float acc[4] = {0.f, 0.f, 0.f, 0.f};

    // per-lane ldmatrix address components
    const int jj = lane & 7, s = lane >> 3;
    const int rowA = m_off + ((s & 1) << 3) + jj;
    const uint32_t dA   = (uint32_t)((s >> 1) << 4);
    const uint32_t xorA = (uint32_t)((rowA & 7) << 4);
    const int rowB = n_off + jj;
    const uint32_t dB   = (uint32_t)((s & 1) << 4);
    const uint32_t xorB = (uint32_t)((rowB & 7) << 4);

    int buf = 0;
    load_chunk(smbase, 0, tid, 0, Wh, Wl, Xh, Xl, Hh, Hl);
    cpcommit();

#pragma unroll 1
    for (int c = 0; c < NCHK; c++) {
        if (c < NCHK - 1) {
            load_chunk(smbase, buf ^ 1, tid, c + 1, Wh, Wl, Xh, Xl, Hh, Hl);
            cpcommit();
            cpwait<1>();
        } else {
            cpwait<0>();
        }
        __syncthreads();

        const uint32_t baseA = smbase + buf * BUFB + rowA * ROWB;
        const uint32_t baseB = smbase + buf * BUFB + 2 * TILEB + rowB * ROWB;
#pragma unroll
        for (int kk = 0; kk < 16; kk++) {
            uint32_t offA = (((uint32_t)(kk << 5)) | dA) ^ xorA;
            uint32_t offB = (((uint32_t)(kk << 5)) | dB) ^ xorB;
            uint32_t ah[4], al[4], bh[2], bl[2];
            ldsm_x4(ah, baseA + offA);
            ldsm_x4(al, baseA + TILEB + offA);
            ldsm_x2(bh, baseB + offB);
            ldsm_x2(bl, baseB + TILEB + offB);
            mma_bf16(acc, ah, bh);
            mma_bf16(acc, ah, bl);
            mma_bf16(acc, al, bh);
        }
        __syncthreads();
        buf ^= 1;
    }

    // write gate tile to smem: G[m][b], stride 33
    {
        float* G = (float*)(smc + G_B);
        const int row0 = m_off + (lane >> 2);
        const int col0 = n_off + ((lane & 3) << 1);
        G[row0 * 33 + col0]           = acc[0];
        G[row0 * 33 + col0 + 1]       = acc[1];
        G[(row0 + 8) * 33 + col0]     = acc[2];
        G[(row0 + 8) * 33 + col0 + 1] = acc[3];
    }
    __syncthreads();

    // elementwise LSTM cell: one (b, uu) per thread
    {
        const int b  = tid >> 3;
        const int uu = tid & 7;
        float* G  = (float*)(smc + G_B);
        float* BS = (float*)(smc + BS_B);
        float* CS = (float*)(smc + CS_B);
        float gi = G[(0 * 8 + uu) * 33 + b] + BS[l * 32 + uu];
        float gf = G[(1 * 8 + uu) * 33 + b] + BS[l * 32 + 8 + uu];
        float gg = G[(2 * 8 + uu) * 33 + b] + BS[l * 32 + 16 + uu];
        float go = G[(3 * 8 + uu) * 33 + b] + BS[l * 32 + 24 + uu];
        float cOld = CS[l * 256 + tid];
        float si = 1.f / (1.f + __expf(-gi));
        float sf = 1.f / (1.f + __expf(-gf));
        float so = 1.f / (1.f + __expf(-go));
        float cN = sf * cOld + si * tanhf(gg);
        float hN = so * tanhf(cN);
        CS[l * 256 + tid] = cN;
        const int u = r * 8 + uu;
        bf16 hi = __float2bfloat16(hN);
        bf16 lo = __float2bfloat16(hN - __bfloat162float(hi));
        st_bf16_cg(&houth[b * H_ + u], hi);
        st_bf16_cg(&houtl[b * H_ + u], lo);
        if (h1out) __stcg(&h1out[b * H_ + u], hN);
    }
    __syncthreads();
}

// ---------------------------------------------------------------------------
// Persistent LSTM kernel
// ---------------------------------------------------------------------------
__global__ void __launch_bounds__(NTHR, 1) lstm_persistent(
    const float* __restrict__ bih, const float* __restrict__ bhh,
    const float* __restrict__ h0)
{
    extern __shared__ char smc[];
    const int tid = threadIdx.x;
    const int r   = blockIdx.x;
    const uint32_t smbase = (uint32_t)__cvta_generic_to_shared(smc);

    // biases for this CTA's 32 gate rows, both layers
    if (tid < 64) {
        int l = tid >> 5, n = tid & 31;
        int j = ((n >> 3) << 10) + (r << 3) + (n & 7);
        ((float*)(smc + BS_B))[tid] = bih[l * 4 * H_ + j] + bhh[l * 4 * H_ + j];
    }
    // init h (global bf16 hi/lo, parity 0) and c (smem) from h0
    {
        const int b = tid >> 3, uu = tid & 7;
        const int u = r * 8 + uu;
        const int base = b * (4 * H_);
        float* CS = (float*)(smc + CS_B);
#pragma unroll
        for (int l = 0; l < 2; l++) {
            float hv = h0[base + l * 2 * H_ + u];
            float cv = h0[base + l * 2 * H_ + H_ + u];
            bf16 hi = __float2bfloat16(hv);
            bf16 lo = __float2bfloat16(hv - __bfloat162float(hi));
            st_bf16_cg(&d_hh[l][0][b * H_ + u], hi);
            st_bf16_cg(&d_hl[l][0][b * H_ + u], lo);
            CS[l * 256 + tid] = cv;
        }
    }
    __syncthreads();

    unsigned gen = 0;
    gridbar(++gen);

    const bf16* Wh0 = d_Wh + (size_t)(0 * 128 + r) * 32 * 2048;
    const bf16* Wl0 = d_Wl + (size_t)(0 * 128 + r) * 32 * 2048;
    const bf16* Wh1 = d_Wh + (size_t)(1 * 128 + r) * 32 * 2048;
    const bf16* Wl1 = d_Wl + (size_t)(1 * 128 + r) * 32 * 2048;

#pragma unroll 1
    for (int t = 0; t < T_; t++) {
        const int p = t & 1;
        // layer 0: Xin = E[t], Hprev = hbuf0[p] -> hbuf0[1-p]
        lstm_phase(smc, smbase, tid, r, 0,
                   Wh0, Wl0,
                   d_Ehi + (size_t)t * B_ * H_, d_Elo + (size_t)t * B_ * H_,
                   d_hh[0][p], d_hl[0][p],
                   d_hh[0][1 - p], d_hl[0][1 - p], (float*)0);
        gridbar(++gen);
        // layer 1: Xin = hbuf0[1-p], Hprev = hbuf1[p] -> hbuf1[1-p], H1[t]
        lstm_phase(smc, smbase, tid, r, 1,
                   Wh1, Wl1,
                   d_hh[0][1 - p], d_hl[0][1 - p],
                   d_hh[1][p], d_hl[1][p],
                   d_hh[1][1 - p], d_hl[1][1 - p],
                   d_H1 + (size_t)t * B_ * H_);
        // barrier for phase1->next handled by next iteration's gridbar
    }
}

// ---------------------------------------------------------------------------
extern "C" void kernel_launch(void* const* d_in, const int* in_sizes, int n_in,
                              void* d_out, int out_size) {
    const float* x       = (const float*)d_in[0];
    const float* W_embed = (const float*)d_in[1];
    const float* b_embed = (const float*)d_in[2];
    const float* W_ih    = (const float*)d_in[3];
    const float* b_ih    = (const float*)d_in[4];
    const float* W_hh    = (const float*)d_in[5];
    const float* b_hh    = (const float*)d_in[6];
    const float* W_out   = (const float*)d_in[7];
    const float* b_out   = (const float*)d_in[8];
    const float* h0      = (const float*)d_in[9];
    float* out = (float*)d_out;

    cudaFuncSetAttribute(lstm_persistent,
                         cudaFuncAttributeMaxDynamicSharedMemorySize, SMEM_BYTES);

    prep_weights<<<dim3(128, 2), 256>>>(W_ih, W_hh);
    embed_kernel<<<dim3(4, T_), 256>>>(x, W_embed, b_embed);
    lstm_persistent<<<NCTA, NTHR, SMEM_BYTES>>>(b_ih, b_hh, h0);
    out_kernel<<<T_, 128>>>(W_out, b_out, out);
}

// round 5
// speedup vs baseline: 2.1217x; 1.0983x over previous
#include <cuda_runtime.h>
#include <cuda_bf16.h>
#include <math.h>
#include <stdint.h>

// Problem dims
#define B_   32
#define T_   512
#define IN_  128
#define H_   1024
#define OUT_ 128

// Persistent kernel config
#define NCTA 128
#define NTHR 256
#define STAGEB 65536            // bytes per pipeline stage: [Whi 16K][Wlo 16K][Ahi 16K][Alo 16K]
#define NSTAGE 3

// SMEM byte offsets
#define G_B   196608            // 32*33 f32 = 4224
#define BS_B  200832            // 64 f32
#define CS_B  201088            // 512 f32
#define MB_B  203136            // 3 mbarriers
#define SMEM_BYTES 203264

typedef __nv_bfloat16 bf16;

// ---------------------------------------------------------------------------
// Device scratch
// ---------------------------------------------------------------------------
__device__ float d_M0  [4096 * 128];            // Wih0 @ W_emb^T
__device__ float d_bv0 [4096];                  // b_emb @ Wih0^T
__device__ float d_G0  [(size_t)T_ * 128 * 32 * 32];   // [t][r][m][b] fp32, 256 MB
__device__ float d_H1  [(size_t)T_ * B_ * H_];  // layer-1 h, fp32, 64 MB
// Swizzled SMEM-image weight blocks: [(l*128+r)][chunk 0..7][hi 16K][lo 16K]
__device__ unsigned char d_Wimg[(size_t)2 * 128 * 8 * 32768];
// Swizzled act images: [parity][chunk 0..3][hi 16K][lo 16K]
__device__ unsigned char d_h0img[2][4 * 32768];
__device__ unsigned char d_h1img[2][4 * 32768];
__device__ unsigned g_arrive;
__device__ unsigned g_release;

// ---------------------------------------------------------------------------
// PTX helpers
// ---------------------------------------------------------------------------
__device__ __forceinline__ void bulk_ld(uint32_t dst, const void* src, uint32_t bytes, uint32_t mbar) {
    asm volatile("cp.async.bulk.shared::cta.global.mbarrier::complete_tx::bytes [%0], [%1], %2, [%3];"
                 :: "r"(dst), "l"(src), "r"(bytes), "r"(mbar) : "memory");
}
__device__ __forceinline__ void mbar_init(uint32_t mbar, uint32_t cnt) {
    asm volatile("mbarrier.init.shared.b64 [%0], %1;" :: "r"(mbar), "r"(cnt) : "memory");
}
__device__ __forceinline__ void mbar_expect(uint32_t mbar, uint32_t tx) {
    asm volatile("mbarrier.arrive.expect_tx.shared.b64 _, [%0], %1;" :: "r"(mbar), "r"(tx) : "memory");
}
__device__ __forceinline__ void mbar_wait(uint32_t mbar, uint32_t ph) {
    asm volatile(
        "{\n\t.reg .pred P;\n\t"
        "WAIT_%=:\n\t"
        "mbarrier.try_wait.parity.shared.b64 P, [%0], %1, 0x989680;\n\t"
        "@P bra.uni DONE_%=;\n\t"
        "bra.uni WAIT_%=;\n\t"
        "DONE_%=:\n\t}"
        :: "r"(mbar), "r"(ph) : "memory");
}
__device__ __forceinline__ void ldsm_x4(uint32_t* r, uint32_t addr) {
    asm volatile("ldmatrix.sync.aligned.m8n8.x4.shared.b16 {%0,%1,%2,%3}, [%4];\n"
                 : "=r"(r[0]), "=r"(r[1]), "=r"(r[2]), "=r"(r[3]) : "r"(addr));
}
__device__ __forceinline__ void ldsm_x2(uint32_t* r, uint32_t addr) {
    asm volatile("ldmatrix.sync.aligned.m8n8.x2.shared.b16 {%0,%1}, [%2];\n"
                 : "=r"(r[0]), "=r"(r[1]) : "r"(addr));
}
__device__ __forceinline__ void mma_bf16(float* c, const uint32_t* a, const uint32_t* b) {
    asm volatile("mma.sync.aligned.m16n8k16.row.col.f32.bf16.bf16.f32 "
                 "{%0,%1,%2,%3}, {%4,%5,%6,%7}, {%8,%9}, {%0,%1,%2,%3};\n"
                 : "+f"(c[0]), "+f"(c[1]), "+f"(c[2]), "+f"(c[3])
                 : "r"(a[0]), "r"(a[1]), "r"(a[2]), "r"(a[3]), "r"(b[0]), "r"(b[1]));
}
// write one activation value into a swizzled chunk-blocked hi/lo image
__device__ __forceinline__ void store_act(unsigned char* img, int b, int u, float v) {
    bf16 hi = __float2bfloat16(v);
    bf16 lo = __float2bfloat16(v - __bfloat162float(hi));
    uint32_t x  = ((uint32_t)(u & 255)) * 2u;
    uint32_t sx = x ^ ((uint32_t)(b & 7) << 4);
    unsigned char* p = img + (((size_t)(u >> 8)) << 15) + (uint32_t)b * 512u + sx;
    unsigned short hb = __bfloat16_as_ushort(hi), lb = __bfloat16_as_ushort(lo);
    asm volatile("st.global.cg.u16 [%0], %1;" :: "l"(p), "h"(hb));
    asm volatile("st.global.cg.u16 [%0], %1;" :: "l"(p + 16384), "h"(lb));
}

// ---------------------------------------------------------------------------
// Grid barrier
// ---------------------------------------------------------------------------
__device__ __forceinline__ void gridbar(unsigned gen) {
    __threadfence();
    __syncthreads();
    if (threadIdx.x == 0) {
        unsigned a = atomicAdd(&g_arrive, 1u) + 1u;
        if (a == (unsigned)NCTA * gen) {
            atomicExch(&g_release, gen);
        } else {
            while (*((volatile unsigned*)&g_release) < gen) __nanosleep(32);
        }
    }
    __syncthreads();
}

// ---------------------------------------------------------------------------
// M0 = Wih0 @ W_emb^T [4096 x 128], bvec0 = Wih0 @ b_emb.  Exact fp32.
// grid 512 blocks x 128 thr, 8 j-rows per block.
// ---------------------------------------------------------------------------
__global__ void m0_kernel(const float* __restrict__ Wih,
                          const float* __restrict__ Wemb,
                          const float* __restrict__ bemb) {
    __shared__ float wih_s[8][1024];
    __shared__ float red[128];
    const int tid = threadIdx.x;
    const int j0  = blockIdx.x * 8;

    if (blockIdx.x == 0 && tid == 0) { g_arrive = 0u; g_release = 0u; }

    for (int i = tid; i < 8 * 1024; i += 128) {
        int jj = i >> 10, k = i & 1023;
        wih_s[jj][k] = Wih[(size_t)(j0 + jj) * 1024 + k];
    }
    __syncthreads();

    float acc[8];
#pragma unroll
    for (int jj = 0; jj < 8; jj++) acc[jj] = 0.f;
    float bp[8];
#pragma unroll
    for (int jj = 0; jj < 8; jj++) bp[jj] = 0.f;

    for (int k = 0; k < 1024; k++) {
        float we = Wemb[k * 128 + tid];
#pragma unroll
        for (int jj = 0; jj < 8; jj++) acc[jj] += wih_s[jj][k] * we;
    }
    for (int k = tid; k < 1024; k += 128) {
        float be = bemb[k];
#pragma unroll
        for (int jj = 0; jj < 8; jj++) bp[jj] += wih_s[jj][k] * be;
    }
#pragma unroll
    for (int jj = 0; jj < 8; jj++) {
        d_M0[(size_t)(j0 + jj) * 128 + tid] = acc[jj];
        __syncthreads();
        red[tid] = bp[jj];
        __syncthreads();
        for (int s = 64; s > 0; s >>= 1) {
            if (tid < s) red[tid] += red[tid + s];
            __syncthreads();
        }
        if (tid == 0) d_bv0[j0 + jj] = red[0];
    }
}

// ---------------------------------------------------------------------------
// G0[t][r][m][b] = x[b][t][:] . M0[j(r,m)][:] + bvec0[j].  grid (128, 512).
// ---------------------------------------------------------------------------
__global__ void g0_kernel(const float* __restrict__ x) {
    __shared__ float xs[32][129];
    const int r = blockIdx.x, t = blockIdx.y;
    const int tid = threadIdx.x;

    for (int i = tid; i < 32 * 128; i += 256) {
        int b = i >> 7, k = i & 127;
        xs[b][k] = x[((size_t)b * T_ + t) * IN_ + k];
    }
    __syncthreads();

    const int m  = tid >> 3;
    const int bq = (tid & 7) * 4;
    const int j  = ((m >> 3) << 10) + (r << 3) + (m & 7);
    const float* M0r = d_M0 + (size_t)j * 128;

    float acc[4];
    const float bv = d_bv0[j];
#pragma unroll
    for (int i = 0; i < 4; i++) acc[i] = bv;

#pragma unroll 4
    for (int k = 0; k < 128; k++) {
        float w = M0r[k];
#pragma unroll
        for (int i = 0; i < 4; i++) acc[i] += w * xs[bq + i][k];
    }
    float4 v = make_float4(acc[0], acc[1], acc[2], acc[3]);
    *(float4*)(d_G0 + (((size_t)t * 128 + r) * 32 + m) * 32 + bq) = v;
}

// ---------------------------------------------------------------------------
// Weight prep: build swizzled hi/lo SMEM images, chunk-blocked per (l, r).
// l=0: chunks 0..3 = Whh0 (K=1024).  l=1: 0..3 = Wih1, 4..7 = Whh1.
// ---------------------------------------------------------------------------
__global__ void prep_weights(const float* __restrict__ Wih,
                             const float* __restrict__ Whh) {
    const int r = blockIdx.x, l = blockIdx.y;
    unsigned char* base = d_Wimg + ((size_t)(l * 128 + r) << 18);

    for (int g = threadIdx.x; g < 8192; g += 256) {
        int c  = g >> 10;
        int m  = (g >> 5) & 31;
        int gk = g & 31;
        if (l == 0 && c >= 4) continue;
        int j = ((m >> 3) << 10) + (r << 3) + (m & 7);
        const float* src;
        if (l == 0)      src = Whh + (size_t)j * 1024 + c * 256 + gk * 8;
        else if (c < 4)  src = Wih + (size_t)(4096 + j) * 1024 + c * 256 + gk * 8;
        else             src = Whh + (size_t)(4096 + j) * 1024 + (c - 4) * 256 + gk * 8;

        float f[8];
        float4 v0 = ((const float4*)src)[0];
        float4 v1 = ((const float4*)src)[1];
        f[0]=v0.x; f[1]=v0.y; f[2]=v0.z; f[3]=v0.w;
        f[4]=v1.x; f[5]=v1.y; f[6]=v1.z; f[7]=v1.w;
        unsigned short hb[8], lb[8];
#pragma unroll
        for (int i = 0; i < 8; i++) {
            bf16 hi = __float2bfloat16(f[i]);
            bf16 lo = __float2bfloat16(f[i] - __bfloat162float(hi));
            hb[i] = __bfloat16_as_ushort(hi);
            lb[i] = __bfloat16_as_ushort(lo);
        }
        uint4 hv, lv;
        hv.x = (uint32_t)hb[0] | ((uint32_t)hb[1] << 16);
        hv.y = (uint32_t)hb[2] | ((uint32_t)hb[3] << 16);
        hv.z = (uint32_t)hb[4] | ((uint32_t)hb[5] << 16);
        hv.w = (uint32_t)hb[6] | ((uint32_t)hb[7] << 16);
        lv.x = (uint32_t)lb[0] | ((uint32_t)lb[1] << 16);
        lv.y = (uint32_t)lb[2] | ((uint32_t)lb[3] << 16);
        lv.z = (uint32_t)lb[4] | ((uint32_t)lb[5] << 16);
        lv.w = (uint32_t)lb[6] | ((uint32_t)lb[7] << 16);
        uint32_t off = (uint32_t)m * 512u + (((uint32_t)gk << 4) ^ ((uint32_t)(m & 7) << 4));
        *(uint4*)(base + ((size_t)c << 15) + off)         = hv;
        *(uint4*)(base + ((size_t)c << 15) + 16384 + off) = lv;
    }
}

// ---------------------------------------------------------------------------
// Output kernel (unchanged): out[b][t][o] = H1[t][b][:] . W_out[o][:] + b_out
// ---------------------------------------------------------------------------
__global__ void out_kernel(const float* __restrict__ Wout,
                           const float* __restrict__ bout,
                           float* __restrict__ out) {
    __shared__ float hs[B_][128];
    const int t   = blockIdx.x;
    const int tid = threadIdx.x;

    float acc[B_];
    const float bv = bout[tid];
#pragma unroll
    for (int b = 0; b < B_; b++) acc[b] = bv;

    for (int kc = 0; kc < H_; kc += 128) {
        __syncthreads();
        for (int i = tid; i < B_ * 128; i += 128) {
            int b = i >> 7, k = i & 127;
            hs[b][k] = d_H1[((size_t)t * B_ + b) * H_ + kc + k];
        }
        __syncthreads();
        const float4* wr = (const float4*)(Wout + tid * H_ + kc);
#pragma unroll 4
        for (int k4 = 0; k4 < 32; k4++) {
            float4 w = wr[k4];
            int k = k4 * 4;
#pragma unroll
            for (int b = 0; b < B_; b++) {
                acc[b] += hs[b][k] * w.x + hs[b][k + 1] * w.y +
                          hs[b][k + 2] * w.z + hs[b][k + 3] * w.w;
            }
        }
    }
#pragma unroll
    for (int b = 0; b < B_; b++) out[((size_t)b * T_ + t) * OUT_ + tid] = acc[b];
}

// ---------------------------------------------------------------------------
// One LSTM phase: nchunks x (2 bulk copies) -> bf16-split mma -> cell.
// ---------------------------------------------------------------------------
__device__ __forceinline__ void do_phase(
    char* smc, uint32_t smbase, int tid, int r, int& q, int& parmask,
    int nchunks,
    const unsigned char* __restrict__ wbase,
    const unsigned char* __restrict__ act0,   // chunks 0..3
    const unsigned char* __restrict__ act1,   // chunks 4..7
    const float* __restrict__ G0row,          // null for layer 1
    int l,
    unsigned char* __restrict__ outimg,
    float* __restrict__ h1out)
{
    const int wid  = tid >> 5;
    const int lane = tid & 31;
    const int m_off = (wid & 1) << 4;
    const int n_off = (wid >> 1) << 3;

    const int jj = lane & 7, s8 = lane >> 3;
    const int rowA = m_off + ((s8 & 1) << 3) + jj;
    const uint32_t dA   = (uint32_t)((s8 >> 1) << 4);
    const uint32_t xorA = (uint32_t)((rowA & 7) << 4);
    const int rowB = n_off + jj;
    const uint32_t dB   = (uint32_t)((s8 & 1) << 4);
    const uint32_t xorB = (uint32_t)((rowB & 7) << 4);

    float acc[4] = {0.f, 0.f, 0.f, 0.f};

    const int pre = nchunks < NSTAGE ? nchunks : NSTAGE;
    if (tid == 0) {
        for (int i = 0; i < pre; i++) {
            int st = (q + i) % NSTAGE;
            uint32_t mb = smbase + MB_B + st * 8;
            const unsigned char* asrc = (i < 4) ? act0 + ((size_t)i << 15)
                                                : act1 + ((size_t)(i - 4) << 15);
            mbar_expect(mb, 65536u);
            bulk_ld(smbase + st * STAGEB,         wbase + ((size_t)i << 15), 32768u, mb);
            bulk_ld(smbase + st * STAGEB + 32768, asrc,                      32768u, mb);
        }
    }

#pragma unroll 1
    for (int c = 0; c < nchunks; c++) {
        const int st = (q + c) % NSTAGE;
        mbar_wait(smbase + MB_B + st * 8, (uint32_t)((parmask >> st) & 1));
        parmask ^= (1 << st);

        const uint32_t sb = smbase + st * STAGEB;
        const uint32_t baseA = sb + rowA * 512;
        const uint32_t baseB = sb + 32768 + rowB * 512;
#pragma unroll
        for (int kk = 0; kk < 16; kk++) {
            uint32_t offA = (((uint32_t)(kk << 5)) | dA) ^ xorA;
            uint32_t offB = (((uint32_t)(kk << 5)) | dB) ^ xorB;
            uint32_t ah[4], al[4], bh[2], bl[2];
            ldsm_x4(ah, baseA + offA);
            ldsm_x4(al, baseA + 16384 + offA);
            ldsm_x2(bh, baseB + offB);
            ldsm_x2(bl, baseB + 16384 + offB);
            mma_bf16(acc, ah, bh);
            mma_bf16(acc, ah, bl);
            mma_bf16(acc, al, bh);
        }
        __syncthreads();   // all lanes done reading stage st

        if (tid == 0 && c + NSTAGE < nchunks) {
            const int c2 = c + NSTAGE;        // (q+c2) % 3 == st
            uint32_t mb = smbase + MB_B + st * 8;
            const unsigned char* asrc = (c2 < 4) ? act0 + ((size_t)c2 << 15)
                                                 : act1 + ((size_t)(c2 - 4) << 15);
            mbar_expect(mb, 65536u);
            bulk_ld(smbase + st * STAGEB,         wbase + ((size_t)c2 << 15), 32768u, mb);
            bulk_ld(smbase + st * STAGEB + 32768, asrc,                       32768u, mb);
        }
    }
    q += nchunks;

    // gate tile -> smem
    {
        float* G = (float*)(smc + G_B);
        const int row0 = m_off + (lane >> 2);
        const int col0 = n_off + ((lane & 3) << 1);
        G[row0 * 33 + col0]           = acc[0];
        G[row0 * 33 + col0 + 1]       = acc[1];
        G[(row0 + 8) * 33 + col0]     = acc[2];
        G[(row0 + 8) * 33 + col0 + 1] = acc[3];
    }
    __syncthreads();

    // elementwise LSTM cell
    {
        const int b  = tid >> 3;
        const int uu = tid & 7;
        float* G  = (float*)(smc + G_B);
        float* BS = (float*)(smc + BS_B);
        float* CS = (float*)(smc + CS_B);
        float gi = G[(0 * 8 + uu) * 33 + b] + BS[l * 32 + uu];
        float gf = G[(1 * 8 + uu) * 33 + b] + BS[l * 32 + 8 + uu];
        float gg = G[(2 * 8 + uu) * 33 + b] + BS[l * 32 + 16 + uu];
        float go = G[(3 * 8 + uu) * 33 + b] + BS[l * 32 + 24 + uu];
        if (G0row) {
            gi += G0row[(0 * 8 + uu) * 32 + b];
            gf += G0row[(1 * 8 + uu) * 32 + b];
            gg += G0row[(2 * 8 + uu) * 32 + b];
            go += G0row[(3 * 8 + uu) * 32 + b];
        }
        float cOld = CS[l * 256 + tid];
        float si = 1.f / (1.f + __expf(-gi));
        float sf = 1.f / (1.f + __expf(-gf));
        float so = 1.f / (1.f + __expf(-go));
        float cN = sf * cOld + si * tanhf(gg);
        float hN = so * tanhf(cN);
        CS[l * 256 + tid] = cN;
        const int u = r * 8 + uu;
        store_act(outimg, b, u, hN);
        if (h1out) __stcg(&h1out[b * H_ + u], hN);
    }
    __syncthreads();
}

// ---------------------------------------------------------------------------
// Persistent LSTM kernel
// ---------------------------------------------------------------------------
__global__ void __launch_bounds__(NTHR, 1) lstm_persistent(
    const float* __restrict__ bih, const float* __restrict__ bhh,
    const float* __restrict__ h0)
{
    extern __shared__ char smc[];
    const int tid = threadIdx.x;
    const int r   = blockIdx.x;
    const uint32_t smbase = (uint32_t)__cvta_generic_to_shared(smc);

    if (tid == 0) {
#pragma unroll
        for (int s = 0; s < NSTAGE; s++) mbar_init(smbase + MB_B + s * 8, 1);
    }
    if (tid < 64) {
        int l = tid >> 5, n = tid & 31;
        int j = ((n >> 3) << 10) + (r << 3) + (n & 7);
        ((float*)(smc + BS_B))[tid] = bih[l * 4 * H_ + j] + bhh[l * 4 * H_ + j];
    }
    {
        const int b = tid >> 3, uu = tid & 7;
        const int u = r * 8 + uu;
        const int base = b * (4 * H_);
        float* CS = (float*)(smc + CS_B);
        float h_l0 = h0[base + 0 * 2 * H_ + u];
        float c_l0 = h0[base + 0 * 2 * H_ + H_ + u];
        float h_l1 = h0[base + 1 * 2 * H_ + u];
        float c_l1 = h0[base + 1 * 2 * H_ + H_ + u];
        store_act(d_h0img[0], b, u, h_l0);
        store_act(d_h1img[0], b, u, h_l1);
        CS[0 * 256 + tid] = c_l0;
        CS[1 * 256 + tid] = c_l1;
    }
    __syncthreads();

    unsigned gen = 0;
    gridbar(++gen);

    const unsigned char* wbase0 = d_Wimg + ((size_t)(0 * 128 + r) << 18);
    const unsigned char* wbase1 = d_Wimg + ((size_t)(1 * 128 + r) << 18);

    int q = 0, parmask = 0;

#pragma unroll 1
    for (int t = 0; t < T_; t++) {
        const int p = t & 1;
        const float* G0row = d_G0 + ((size_t)t * 128 + r) * 1024;
        // layer 0: gates = G0[t] + h0(prev) . Whh0^T   (K = 1024, 4 chunks)
        do_phase(smc, smbase, tid, r, q, parmask, 4,
                 wbase0, d_h0img[p], d_h0img[p], G0row, 0,
                 d_h0img[1 - p], (float*)0);
        gridbar(++gen);
        // layer 1: gates = [h0(t) | h1(prev)] . [Wih1 | Whh1]^T  (K = 2048)
        do_phase(smc, smbase, tid, r, q, parmask, 8,
                 wbase1, d_h0img[1 - p], d_h1img[p], (const float*)0, 1,
                 d_h1img[1 - p], d_H1 + (size_t)t * B_ * H_);
    }
}

// ---------------------------------------------------------------------------
extern "C" void kernel_launch(void* const* d_in, const int* in_sizes, int n_in,
                              void* d_out, int out_size) {
    const float* x       = (const float*)d_in[0];
    const float* W_embed = (const float*)d_in[1];
    const float* b_embed = (const float*)d_in[2];
    const float* W_ih    = (const float*)d_in[3];
    const float* b_ih    = (const float*)d_in[4];
    const float* W_hh    = (const float*)d_in[5];
    const float* b_hh    = (const float*)d_in[6];
    const float* W_out   = (const float*)d_in[7];
    const float* b_out   = (const float*)d_in[8];
    const float* h0      = (const float*)d_in[9];
    float* out = (float*)d_out;

    cudaFuncSetAttribute(lstm_persistent,
                         cudaFuncAttributeMaxDynamicSharedMemorySize, SMEM_BYTES);

    m0_kernel<<<512, 128>>>(W_ih, W_embed, b_embed);
    prep_weights<<<dim3(128, 2), 256>>>(W_ih, W_hh);
    g0_kernel<<<dim3(128, T_), 256>>>(x);
    lstm_persistent<<<NCTA, NTHR, SMEM_BYTES>>>(b_ih, b_hh, h0);
    out_kernel<<<T_, 128>>>(W_out, b_out, out);
}